// round 1
// baseline (speedup 1.0000x reference)
#include <cuda_runtime.h>
#include <cuda_bf16.h>

// LiDAR volume renderer, fused. N=8192 rays, S=512 steps, H=32, OUT=2.
//
// reference math (jax):
//   z_s   = 0.01 + 0.8 * s/511
//   xyz   = clamp(ro + rd*z, -1, 1)
//   h     = relu([xyz,t] @ W1 + b1)                       (4 -> 32)
//   sigma = softplus(h @ Wsig)
//   feat  = h @ Wfeat                                     (32 -> 16)
//   a     = relu([xyz, rd, feat] @ Wa1 + ba1)             (22 -> 32)
//   attr  = sigmoid(a @ Wa2)                              (32 -> 2)
//   delta_s = 0.8/511 (s<511), 0.8/512 (s=511)
//   alpha = 1 - exp(-delta*sigma)
//   w_s   = alpha_s * prod_{j<s}(1-alpha_j + 1e-15)
//   depth = sum w*z ; image = sum w*attr ; wsum = sum w
//
// Fusions:
//   Wc   = Wfeat @ Wa1[6:22]   (32x32, precomputed per launch)
//   b1t  = b1 + t * W1[3]      (t is a scalar input)
//   dirb = ba1 + rd @ Wa1[3:6] (per ray, computed once per warp)

#define NSTEPS 512
#define CHUNKS 16   // 16 chunks x 32 lanes = 512 steps

__device__ float g_Wc[32 * 32];
__device__ float g_b1t[32];

// ---------------------------------------------------------------------------
// Pre-kernel: fold Wfeat @ Wa1[6:22] into one 32x32 matrix; fold time into b1.
// ---------------------------------------------------------------------------
__global__ void lidar_precompute_kernel(const float* __restrict__ W1,
                                        const float* __restrict__ b1,
                                        const float* __restrict__ timep,
                                        const float* __restrict__ Wfeat,
                                        const float* __restrict__ Wa1) {
    int i = threadIdx.x;          // 0..1023
    int r = i >> 5;               // h index   (row of Wfeat)
    int c = i & 31;               // out index (col of Wa1)
    float acc = 0.f;
#pragma unroll
    for (int k = 0; k < 16; k++)
        acc = fmaf(Wfeat[r * 16 + k], Wa1[(6 + k) * 32 + c], acc);
    g_Wc[i] = acc;
    if (i < 32)
        g_b1t[i] = fmaf(timep[0], W1[3 * 32 + i], b1[i]);
}

// ---------------------------------------------------------------------------
// Main kernel: one warp per ray. 8 warps / block (256 threads).
// ---------------------------------------------------------------------------
__global__ __launch_bounds__(256)
void lidar_render_kernel(const float* __restrict__ rays_o,
                         const float* __restrict__ rays_d,
                         const float* __restrict__ W1,
                         const float* __restrict__ Wsig,
                         const float* __restrict__ Wa1,
                         const float* __restrict__ ba1,
                         const float* __restrict__ Wa2,
                         float* __restrict__ out, int N) {
    // weights in shared, float4-addressable (all reads are warp-uniform broadcasts)
    __shared__ float4 sW1r0[8], sW1r1[8], sW1r2[8], sb1t4[8], sWsig4[8];
    __shared__ float4 sWa1x0[8], sWa1x1[8], sWa1x2[8];
    __shared__ float  sWa1d[3][32], sba1[32];
    __shared__ float4 sWa2a4[8], sWa2b4[8];
    __shared__ float4 sWc4[32 * 8];        // Wc[j][i], row j contiguous
    __shared__ float4 sdirb4[8][8];        // per-warp attr bias (dir part + ba1)

    const int tid = threadIdx.x;
    if (tid < 32) {
        ((float*)sW1r0)[tid]  = W1[tid];
        ((float*)sW1r1)[tid]  = W1[32 + tid];
        ((float*)sW1r2)[tid]  = W1[64 + tid];
        ((float*)sb1t4)[tid]  = g_b1t[tid];
        ((float*)sWsig4)[tid] = Wsig[tid];
        ((float*)sWa1x0)[tid] = Wa1[tid];
        ((float*)sWa1x1)[tid] = Wa1[32 + tid];
        ((float*)sWa1x2)[tid] = Wa1[64 + tid];
        sWa1d[0][tid] = Wa1[96 + tid];
        sWa1d[1][tid] = Wa1[128 + tid];
        sWa1d[2][tid] = Wa1[160 + tid];
        sba1[tid] = ba1[tid];
        ((float*)sWa2a4)[tid] = Wa2[tid * 2 + 0];
        ((float*)sWa2b4)[tid] = Wa2[tid * 2 + 1];
    }
    for (int i = tid; i < 1024; i += 256)
        ((float*)sWc4)[i] = g_Wc[i];
    __syncthreads();

    const int warp = tid >> 5;
    const int lane = tid & 31;
    const int ray  = blockIdx.x * 8 + warp;
    if (ray >= N) return;

    const float ox = rays_o[ray * 3 + 0];
    const float oy = rays_o[ray * 3 + 1];
    const float oz = rays_o[ray * 3 + 2];
    const float dx = rays_d[ray * 3 + 0];
    const float dy = rays_d[ray * 3 + 1];
    const float dz = rays_d[ray * 3 + 2];

    // per-ray attr-layer bias: ba1 + rd @ Wa1[3:6]  (lane j computes entry j)
    ((float*)sdirb4[warp])[lane] =
        sba1[lane]
        + dx * sWa1d[0][lane] + dy * sWa1d[1][lane] + dz * sWa1d[2][lane];
    __syncwarp();

    const float ZSTEP = 0.8f / 511.f;
    float Tcarry = 1.f;
    float depth = 0.f, img0 = 0.f, img1 = 0.f, wsum = 0.f;

#pragma unroll 1
    for (int chunk = 0; chunk < CHUNKS; chunk++) {
        const int   s = chunk * 32 + lane;
        const float z = fmaf(ZSTEP, (float)s, 0.01f);
        const float x  = fminf(fmaxf(fmaf(dx, z, ox), -1.f), 1.f);
        const float y  = fminf(fmaxf(fmaf(dy, z, oy), -1.f), 1.f);
        const float zc = fminf(fmaxf(fmaf(dz, z, oz), -1.f), 1.f);

        // --- density MLP hidden layer + sigma head ---
        float h[32];
        float sig = 0.f;
#pragma unroll
        for (int j4 = 0; j4 < 8; j4++) {
            const float4 w0 = sW1r0[j4], w1 = sW1r1[j4], w2 = sW1r2[j4];
            const float4 bb = sb1t4[j4], wsg = sWsig4[j4];
            float v;
            v = fmaf(x, w0.x, fmaf(y, w1.x, fmaf(zc, w2.x, bb.x)));
            v = fmaxf(v, 0.f); h[j4 * 4 + 0] = v; sig = fmaf(v, wsg.x, sig);
            v = fmaf(x, w0.y, fmaf(y, w1.y, fmaf(zc, w2.y, bb.y)));
            v = fmaxf(v, 0.f); h[j4 * 4 + 1] = v; sig = fmaf(v, wsg.y, sig);
            v = fmaf(x, w0.z, fmaf(y, w1.z, fmaf(zc, w2.z, bb.z)));
            v = fmaxf(v, 0.f); h[j4 * 4 + 2] = v; sig = fmaf(v, wsg.z, sig);
            v = fmaf(x, w0.w, fmaf(y, w1.w, fmaf(zc, w2.w, bb.w)));
            v = fmaxf(v, 0.f); h[j4 * 4 + 3] = v; sig = fmaf(v, wsg.w, sig);
        }
        // softplus (stable) -> alpha
        const float sigma = fmaxf(sig, 0.f) + log1pf(__expf(-fabsf(sig)));
        const float delta = (s == NSTEPS - 1) ? (0.8f / 512.f) : ZSTEP;
        float q = __expf(-delta * sigma);   // 1 - alpha
        const float alpha = 1.f - q;
        q += 1e-15f;

        // --- attribute MLP: acc = dirb + xyz@Wa1[0:3] + h@Wc ---
        float acc[32];
#pragma unroll
        for (int i4 = 0; i4 < 8; i4++) {
            const float4 db = sdirb4[warp][i4];
            const float4 wx = sWa1x0[i4], wy = sWa1x1[i4], wz = sWa1x2[i4];
            acc[i4 * 4 + 0] = fmaf(x, wx.x, fmaf(y, wy.x, fmaf(zc, wz.x, db.x)));
            acc[i4 * 4 + 1] = fmaf(x, wx.y, fmaf(y, wy.y, fmaf(zc, wz.y, db.y)));
            acc[i4 * 4 + 2] = fmaf(x, wx.z, fmaf(y, wy.z, fmaf(zc, wz.z, db.z)));
            acc[i4 * 4 + 3] = fmaf(x, wx.w, fmaf(y, wy.w, fmaf(zc, wz.w, db.w)));
        }
#pragma unroll
        for (int j = 0; j < 32; j++) {
            const float hj = h[j];
#pragma unroll
            for (int i4 = 0; i4 < 8; i4++) {
                const float4 wv = sWc4[j * 8 + i4];
                acc[i4 * 4 + 0] = fmaf(hj, wv.x, acc[i4 * 4 + 0]);
                acc[i4 * 4 + 1] = fmaf(hj, wv.y, acc[i4 * 4 + 1]);
                acc[i4 * 4 + 2] = fmaf(hj, wv.z, acc[i4 * 4 + 2]);
                acc[i4 * 4 + 3] = fmaf(hj, wv.w, acc[i4 * 4 + 3]);
            }
        }
        float o0 = 0.f, o1 = 0.f;
#pragma unroll
        for (int i4 = 0; i4 < 8; i4++) {
            const float4 wa = sWa2a4[i4], wb = sWa2b4[i4];
            float v;
            v = fmaxf(acc[i4 * 4 + 0], 0.f); o0 = fmaf(v, wa.x, o0); o1 = fmaf(v, wb.x, o1);
            v = fmaxf(acc[i4 * 4 + 1], 0.f); o0 = fmaf(v, wa.y, o0); o1 = fmaf(v, wb.y, o1);
            v = fmaxf(acc[i4 * 4 + 2], 0.f); o0 = fmaf(v, wa.z, o0); o1 = fmaf(v, wb.z, o1);
            v = fmaxf(acc[i4 * 4 + 3], 0.f); o0 = fmaf(v, wa.w, o0); o1 = fmaf(v, wb.w, o1);
        }
        const float a0 = 1.f / (1.f + __expf(-o0));
        const float a1 = 1.f / (1.f + __expf(-o1));

        // --- transmittance: inclusive warp product-scan of q ---
        float P = q;
#pragma unroll
        for (int off = 1; off < 32; off <<= 1) {
            const float v = __shfl_up_sync(0xffffffffu, P, off);
            if (lane >= off) P *= v;
        }
        float Pexcl = __shfl_up_sync(0xffffffffu, P, 1);
        if (lane == 0) Pexcl = 1.f;

        const float w = alpha * Tcarry * Pexcl;
        depth = fmaf(w, z, depth);
        img0  = fmaf(w, a0, img0);
        img1  = fmaf(w, a1, img1);
        wsum += w;

        Tcarry *= __shfl_sync(0xffffffffu, P, 31);
    }

    // warp reduction, lane 0 writes
#pragma unroll
    for (int off = 16; off; off >>= 1) {
        depth += __shfl_xor_sync(0xffffffffu, depth, off);
        img0  += __shfl_xor_sync(0xffffffffu, img0, off);
        img1  += __shfl_xor_sync(0xffffffffu, img1, off);
        wsum  += __shfl_xor_sync(0xffffffffu, wsum, off);
    }
    if (lane == 0) {
        out[ray]                 = depth;          // depth   [N]
        out[N + ray * 2 + 0]     = img0;           // image   [N,2]
        out[N + ray * 2 + 1]     = img1;
        out[3 * N + ray]         = wsum;           // weights_sum [N]
    }
}

// ---------------------------------------------------------------------------
// Launch. Inputs (metadata order):
// 0 rays_o  1 rays_d  2 time  3 W1  4 b1  5 Wsig  6 Wfeat  7 Wa1  8 ba1
// 9 Wa2  10 num_steps
// ---------------------------------------------------------------------------
extern "C" void kernel_launch(void* const* d_in, const int* in_sizes, int n_in,
                              void* d_out, int out_size) {
    const float* rays_o = (const float*)d_in[0];
    const float* rays_d = (const float*)d_in[1];
    const float* timep  = (const float*)d_in[2];
    const float* W1     = (const float*)d_in[3];
    const float* b1     = (const float*)d_in[4];
    const float* Wsig   = (const float*)d_in[5];
    const float* Wfeat  = (const float*)d_in[6];
    const float* Wa1    = (const float*)d_in[7];
    const float* ba1    = (const float*)d_in[8];
    const float* Wa2    = (const float*)d_in[9];

    const int N = in_sizes[0] / 3;   // 8192

    lidar_precompute_kernel<<<1, 1024>>>(W1, b1, timep, Wfeat, Wa1);
    lidar_render_kernel<<<(N + 7) / 8, 256>>>(rays_o, rays_d, W1, Wsig, Wa1,
                                              ba1, Wa2, (float*)d_out, N);
}

// round 3
// speedup vs baseline: 1.1906x; 1.1906x over previous
#include <cuda_runtime.h>
#include <cuda_bf16.h>

// LiDAR volume renderer, fused, FFMA2 (packed f32x2) version.
// N=8192 rays, S=512 steps, H=32, OUT=2. One warp per ray, 16 chunks of 32.
//
// Fusions:
//   Wc   = Wfeat @ Wa1[6:22]   (32x32, precomputed per launch)
//   b1t  = b1 + t * W1[3]
//   dirb = ba1 + rd @ Wa1[3:6] (per ray)
// All inner matvecs use fma.rn.f32x2 (2 fp32 FMA / issue on sm_103a).

#define NSTEPS 512
#define CHUNKS 16

typedef unsigned long long u64;

__device__ float g_Wc[32 * 32];
__device__ float g_b1t[32];

// ---------------------------------------------------------------------------
__global__ void lidar_precompute_kernel(const float* __restrict__ W1,
                                        const float* __restrict__ b1,
                                        const float* __restrict__ timep,
                                        const float* __restrict__ Wfeat,
                                        const float* __restrict__ Wa1) {
    int i = threadIdx.x;          // 0..1023
    int r = i >> 5;
    int c = i & 31;
    float acc = 0.f;
#pragma unroll
    for (int k = 0; k < 16; k++)
        acc = fmaf(Wfeat[r * 16 + k], Wa1[(6 + k) * 32 + c], acc);
    g_Wc[i] = acc;
    if (i < 32)
        g_b1t[i] = fmaf(timep[0], W1[3 * 32 + i], b1[i]);
}

// ---------------------------------------------------------------------------
// packed f32x2 helpers
// ---------------------------------------------------------------------------
__device__ __forceinline__ u64 pk2(float a, float b) {
    u64 r; asm("mov.b64 %0,{%1,%2};" : "=l"(r) : "f"(a), "f"(b)); return r;
}
__device__ __forceinline__ float2 up2(u64 v) {
    float2 f; asm("mov.b64 {%0,%1},%2;" : "=f"(f.x), "=f"(f.y) : "l"(v)); return f;
}
__device__ __forceinline__ u64 ffma2(u64 a, u64 b, u64 c) {
    u64 d; asm("fma.rn.f32x2 %0,%1,%2,%3;" : "=l"(d) : "l"(a), "l"(b), "l"(c)); return d;
}
__device__ __forceinline__ void lds16(unsigned a, u64& p0, u64& p1) {
    asm volatile("ld.shared.v2.b64 {%0,%1},[%2];" : "=l"(p0), "=l"(p1) : "r"(a));
}

struct __align__(16) Smem {
    float W1r0[32], W1r1[32], W1r2[32], b1t[32], Wsig[32];
    float Wa1x0[32], Wa1x1[32], Wa1x2[32];
    float Wa2a[32], Wa2b[32];
    float Wa1d0[32], Wa1d1[32], Wa1d2[32], ba1[32];
    float Wc[1024];
    float dirb[4][32];
};

// ---------------------------------------------------------------------------
// Main kernel: one warp per ray, 4 warps / block (128 threads).
// ---------------------------------------------------------------------------
__global__ __launch_bounds__(128, 3)
void lidar_render_kernel(const float* __restrict__ rays_o,
                         const float* __restrict__ rays_d,
                         const float* __restrict__ Wsig,
                         const float* __restrict__ Wa1,
                         const float* __restrict__ ba1,
                         const float* __restrict__ Wa2,
                         float* __restrict__ out, int N) {
    __shared__ Smem sm;

    const int tid = threadIdx.x;
    if (tid < 32) {
        // Wa1 rows: [0:3) xyz, [3:6) dir; W1 rows 0..2 from global W1 are
        // passed via g_b1t path? No: W1 first 3 rows come from Wa1 arg order —
        // we pass W1 through rays-side pointers below. (W1 pointer reused.)
    }
    // NOTE: W1 pointer is smuggled via Wsig-4? -- keep explicit instead.
    (void)0;

    // ---- cooperative weight staging ----
    // (W1 passed as separate param; see loader below)
    extern __shared__ int _dummy[]; (void)_dummy;

    const int warp = tid >> 5;
    const int lane = tid & 31;
    const int ray  = blockIdx.x * 4 + warp;

    // loader uses the real params; done in kernel_launch-ordered args:
    // we re-declare them here for clarity (see parameter list).
    // ---- actual staging is done in the wrapper section below ----

    // placeholder to keep compiler happy (real code continues in part 2)
    // (This comment block intentionally inert.)

    // ---- staging ----
    // staged via the extra param trick: see lidar_render_kernel2.
    if (false) { out[0] = rays_o[0] + rays_d[0] + Wsig[0] + Wa1[0] + ba1[0] + Wa2[0] + (float)N; }
    (void)warp; (void)lane; (void)ray;
}

// The real kernel (single, clean definition).
__global__ __launch_bounds__(128, 3)
void lidar_render(const float* __restrict__ rays_o,
                  const float* __restrict__ rays_d,
                  const float* __restrict__ W1,
                  const float* __restrict__ Wsig,
                  const float* __restrict__ Wa1,
                  const float* __restrict__ ba1,
                  const float* __restrict__ Wa2,
                  float* __restrict__ out, int N) {
    __shared__ Smem sm;
    const int tid = threadIdx.x;

    if (tid < 32) {
        sm.W1r0[tid]  = W1[tid];
        sm.W1r1[tid]  = W1[32 + tid];
        sm.W1r2[tid]  = W1[64 + tid];
        sm.b1t[tid]   = g_b1t[tid];
        sm.Wsig[tid]  = Wsig[tid];
        sm.Wa1x0[tid] = Wa1[tid];
        sm.Wa1x1[tid] = Wa1[32 + tid];
        sm.Wa1x2[tid] = Wa1[64 + tid];
        sm.Wa1d0[tid] = Wa1[96 + tid];
        sm.Wa1d1[tid] = Wa1[128 + tid];
        sm.Wa1d2[tid] = Wa1[160 + tid];
        sm.ba1[tid]   = ba1[tid];
        sm.Wa2a[tid]  = Wa2[tid * 2 + 0];
        sm.Wa2b[tid]  = Wa2[tid * 2 + 1];
    }
    for (int i = tid; i < 1024; i += 128)
        sm.Wc[i] = g_Wc[i];
    __syncthreads();

    const int warp = tid >> 5;
    const int lane = tid & 31;
    const int ray  = blockIdx.x * 4 + warp;
    if (ray >= N) return;

    const float ox = rays_o[ray * 3 + 0];
    const float oy = rays_o[ray * 3 + 1];
    const float oz = rays_o[ray * 3 + 2];
    const float dx = rays_d[ray * 3 + 0];
    const float dy = rays_d[ray * 3 + 1];
    const float dz = rays_d[ray * 3 + 2];

    // per-ray attr bias: ba1 + rd @ Wa1[3:6]
    sm.dirb[warp][lane] = sm.ba1[lane]
        + dx * sm.Wa1d0[lane] + dy * sm.Wa1d1[lane] + dz * sm.Wa1d2[lane];
    __syncwarp();

    // shared byte addresses for asm LDS
    const unsigned aW1r0 = (unsigned)__cvta_generic_to_shared(sm.W1r0);
    const unsigned aW1r1 = (unsigned)__cvta_generic_to_shared(sm.W1r1);
    const unsigned aW1r2 = (unsigned)__cvta_generic_to_shared(sm.W1r2);
    const unsigned ab1t  = (unsigned)__cvta_generic_to_shared(sm.b1t);
    const unsigned aWsig = (unsigned)__cvta_generic_to_shared(sm.Wsig);
    const unsigned aWx0  = (unsigned)__cvta_generic_to_shared(sm.Wa1x0);
    const unsigned aWx1  = (unsigned)__cvta_generic_to_shared(sm.Wa1x1);
    const unsigned aWx2  = (unsigned)__cvta_generic_to_shared(sm.Wa1x2);
    const unsigned aWa2a = (unsigned)__cvta_generic_to_shared(sm.Wa2a);
    const unsigned aWa2b = (unsigned)__cvta_generic_to_shared(sm.Wa2b);
    const unsigned aWc   = (unsigned)__cvta_generic_to_shared(sm.Wc);
    const unsigned adirb = (unsigned)__cvta_generic_to_shared(sm.dirb[warp]);

    const float ZSTEP = 0.8f / 511.f;
    float Tcarry = 1.f;
    float depth = 0.f, img0 = 0.f, img1 = 0.f, wsum = 0.f;

#pragma unroll 1
    for (int chunk = 0; chunk < CHUNKS; chunk++) {
        const int   s = chunk * 32 + lane;
        const float z = fmaf(ZSTEP, (float)s, 0.01f);
        const float x  = fminf(fmaxf(fmaf(dx, z, ox), -1.f), 1.f);
        const float y  = fminf(fmaxf(fmaf(dy, z, oy), -1.f), 1.f);
        const float zc = fminf(fmaxf(fmaf(dz, z, oz), -1.f), 1.f);

        const u64 xx = pk2(x, x), yy = pk2(y, y), zz = pk2(zc, zc);

        // --- density hidden layer (packed) + sigma head ---
        float h[32];
        u64 sig2 = 0ULL;   // (0.f, 0.f)
#pragma unroll
        for (int k = 0; k < 8; k++) {
            u64 w0a, w0b, w1a, w1b, w2a, w2b, ba, bb, sa, sb;
            lds16(aW1r0 + k * 16, w0a, w0b);
            lds16(aW1r1 + k * 16, w1a, w1b);
            lds16(aW1r2 + k * 16, w2a, w2b);
            lds16(ab1t  + k * 16, ba, bb);
            u64 v0 = ffma2(xx, w0a, ffma2(yy, w1a, ffma2(zz, w2a, ba)));
            u64 v1 = ffma2(xx, w0b, ffma2(yy, w1b, ffma2(zz, w2b, bb)));
            float2 f0 = up2(v0), f1 = up2(v1);
            f0.x = fmaxf(f0.x, 0.f); f0.y = fmaxf(f0.y, 0.f);
            f1.x = fmaxf(f1.x, 0.f); f1.y = fmaxf(f1.y, 0.f);
            h[4 * k + 0] = f0.x; h[4 * k + 1] = f0.y;
            h[4 * k + 2] = f1.x; h[4 * k + 3] = f1.y;
            lds16(aWsig + k * 16, sa, sb);
            sig2 = ffma2(pk2(f0.x, f0.y), sa, sig2);
            sig2 = ffma2(pk2(f1.x, f1.y), sb, sig2);
        }
        const float2 sg = up2(sig2);
        const float sig = sg.x + sg.y;

        // softplus (stable) -> alpha
        const float sigma = fmaxf(sig, 0.f) + log1pf(__expf(-fabsf(sig)));
        const float delta = (s == NSTEPS - 1) ? (0.8f / 512.f) : ZSTEP;
        float q = __expf(-delta * sigma);   // 1 - alpha
        const float alpha = 1.f - q;
        q += 1e-15f;

        // --- attr MLP: acc = dirb + xyz @ Wa1[0:3] + h @ Wc (packed) ---
        u64 acc[16];
#pragma unroll
        for (int k = 0; k < 8; k++) {
            u64 xa, xb, ya, yb, za, zb, da, db;
            lds16(aWx0 + k * 16, xa, xb);
            lds16(aWx1 + k * 16, ya, yb);
            lds16(aWx2 + k * 16, za, zb);
            lds16(adirb + k * 16, da, db);
            acc[2 * k + 0] = ffma2(xx, xa, ffma2(yy, ya, ffma2(zz, za, da)));
            acc[2 * k + 1] = ffma2(xx, xb, ffma2(yy, yb, ffma2(zz, zb, db)));
        }
#pragma unroll
        for (int j = 0; j < 32; j++) {
            const u64 hjj = pk2(h[j], h[j]);
            const unsigned row = aWc + j * 128;
#pragma unroll
            for (int m = 0; m < 4; m++) {
                u64 p0, p1, p2, p3;
                lds16(row + m * 32, p0, p1);
                lds16(row + m * 32 + 16, p2, p3);
                acc[4 * m + 0] = ffma2(hjj, p0, acc[4 * m + 0]);
                acc[4 * m + 1] = ffma2(hjj, p1, acc[4 * m + 1]);
                acc[4 * m + 2] = ffma2(hjj, p2, acc[4 * m + 2]);
                acc[4 * m + 3] = ffma2(hjj, p3, acc[4 * m + 3]);
            }
        }

        // --- attr head: relu then @ Wa2 (packed) ---
        u64 o0p = 0ULL, o1p = 0ULL;
#pragma unroll
        for (int k = 0; k < 8; k++) {
            u64 wa0, wa1v, wb0, wb1v;
            lds16(aWa2a + k * 16, wa0, wa1v);
            lds16(aWa2b + k * 16, wb0, wb1v);
            float2 q0 = up2(acc[2 * k + 0]), q1 = up2(acc[2 * k + 1]);
            q0.x = fmaxf(q0.x, 0.f); q0.y = fmaxf(q0.y, 0.f);
            q1.x = fmaxf(q1.x, 0.f); q1.y = fmaxf(q1.y, 0.f);
            const u64 r0 = pk2(q0.x, q0.y), r1 = pk2(q1.x, q1.y);
            o0p = ffma2(r0, wa0, o0p); o0p = ffma2(r1, wa1v, o0p);
            o1p = ffma2(r0, wb0, o1p); o1p = ffma2(r1, wb1v, o1p);
        }
        const float2 t0 = up2(o0p), t1 = up2(o1p);
        const float a0 = 1.f / (1.f + __expf(-(t0.x + t0.y)));
        const float a1 = 1.f / (1.f + __expf(-(t1.x + t1.y)));

        // --- transmittance: inclusive warp product-scan of q ---
        float P = q;
#pragma unroll
        for (int off = 1; off < 32; off <<= 1) {
            const float v = __shfl_up_sync(0xffffffffu, P, off);
            if (lane >= off) P *= v;
        }
        float Pexcl = __shfl_up_sync(0xffffffffu, P, 1);
        if (lane == 0) Pexcl = 1.f;

        const float w = alpha * Tcarry * Pexcl;
        depth = fmaf(w, z, depth);
        img0  = fmaf(w, a0, img0);
        img1  = fmaf(w, a1, img1);
        wsum += w;

        Tcarry *= __shfl_sync(0xffffffffu, P, 31);
    }

    // warp reduction, lane 0 writes
#pragma unroll
    for (int off = 16; off; off >>= 1) {
        depth += __shfl_xor_sync(0xffffffffu, depth, off);
        img0  += __shfl_xor_sync(0xffffffffu, img0, off);
        img1  += __shfl_xor_sync(0xffffffffu, img1, off);
        wsum  += __shfl_xor_sync(0xffffffffu, wsum, off);
    }
    if (lane == 0) {
        out[ray]             = depth;        // depth        [N]
        out[N + ray * 2 + 0] = img0;         // image        [N,2]
        out[N + ray * 2 + 1] = img1;
        out[3 * N + ray]     = wsum;         // weights_sum  [N]
    }
}

// ---------------------------------------------------------------------------
// Launch. Inputs (metadata order):
// 0 rays_o  1 rays_d  2 time  3 W1  4 b1  5 Wsig  6 Wfeat  7 Wa1  8 ba1
// 9 Wa2  10 num_steps
// ---------------------------------------------------------------------------
extern "C" void kernel_launch(void* const* d_in, const int* in_sizes, int n_in,
                              void* d_out, int out_size) {
    const float* rays_o = (const float*)d_in[0];
    const float* rays_d = (const float*)d_in[1];
    const float* timep  = (const float*)d_in[2];
    const float* W1     = (const float*)d_in[3];
    const float* b1     = (const float*)d_in[4];
    const float* Wsig   = (const float*)d_in[5];
    const float* Wfeat  = (const float*)d_in[6];
    const float* Wa1    = (const float*)d_in[7];
    const float* ba1    = (const float*)d_in[8];
    const float* Wa2    = (const float*)d_in[9];

    const int N = in_sizes[0] / 3;   // 8192

    lidar_precompute_kernel<<<1, 1024>>>(W1, b1, timep, Wfeat, Wa1);
    lidar_render<<<(N + 3) / 4, 128>>>(rays_o, rays_d, W1, Wsig, Wa1,
                                       ba1, Wa2, (float*)d_out, N);
}

// round 5
// speedup vs baseline: 1.7087x; 1.4352x over previous
#include <cuda_runtime.h>
#include <cuda_bf16.h>

// LiDAR volume renderer, fused, FFMA2 (packed f32x2), 2 steps per lane.
// N=8192 rays, S=512 steps, H=32, OUT=2. One warp per ray.
// 8 fused chunks x 64 steps; lane handles steps (c*64+lane) and (c*64+32+lane)
// so every warp-uniform weight LDS feeds both steps (halves LDS pressure,
// which R2 ncu showed as the binding resource: L1=91.6%).
//
// Fusions:
//   Wc   = Wfeat @ Wa1[6:22]   (32x32, precomputed per launch)
//   b1t  = b1 + t * W1[3]
//   dirb = ba1 + rd @ Wa1[3:6] (per ray)

#define CHUNKS 8

typedef unsigned long long u64;

__device__ float g_Wc[32 * 32];
__device__ float g_b1t[32];

// ---------------------------------------------------------------------------
__global__ void lidar_precompute_kernel(const float* __restrict__ W1,
                                        const float* __restrict__ b1,
                                        const float* __restrict__ timep,
                                        const float* __restrict__ Wfeat,
                                        const float* __restrict__ Wa1) {
    int i = threadIdx.x;          // 0..1023
    int r = i >> 5;
    int c = i & 31;
    float acc = 0.f;
#pragma unroll
    for (int k = 0; k < 16; k++)
        acc = fmaf(Wfeat[r * 16 + k], Wa1[(6 + k) * 32 + c], acc);
    g_Wc[i] = acc;
    if (i < 32)
        g_b1t[i] = fmaf(timep[0], W1[3 * 32 + i], b1[i]);
}

// ---------------------------------------------------------------------------
// packed f32x2 helpers
// ---------------------------------------------------------------------------
__device__ __forceinline__ u64 pk2(float a, float b) {
    u64 r; asm("mov.b64 %0,{%1,%2};" : "=l"(r) : "f"(a), "f"(b)); return r;
}
__device__ __forceinline__ float2 up2(u64 v) {
    float2 f; asm("mov.b64 {%0,%1},%2;" : "=f"(f.x), "=f"(f.y) : "l"(v)); return f;
}
__device__ __forceinline__ u64 ffma2(u64 a, u64 b, u64 c) {
    u64 d; asm("fma.rn.f32x2 %0,%1,%2,%3;" : "=l"(d) : "l"(a), "l"(b), "l"(c)); return d;
}
__device__ __forceinline__ void lds16(unsigned a, u64& p0, u64& p1) {
    asm volatile("ld.shared.v2.b64 {%0,%1},[%2];" : "=l"(p0), "=l"(p1) : "r"(a));
}
__device__ __forceinline__ u64 relu2(u64 v) {
    float2 f = up2(v);
    return pk2(fmaxf(f.x, 0.f), fmaxf(f.y, 0.f));
}

// smem layout: BYTE offsets, each block 128B-aligned
#define O_W1R0  0u
#define O_W1R1  128u
#define O_W1R2  256u
#define O_B1T   384u
#define O_WSIG  512u
#define O_WX0   640u
#define O_WX1   768u
#define O_WX2   896u
#define O_WA2A  1024u
#define O_WA2B  1152u
#define O_WD0   1280u
#define O_WD1   1408u
#define O_WD2   1536u
#define O_BA1   1664u
#define O_WC    1792u          // 4096 bytes
#define O_DIRB  5888u          // 4 warps x 128B
#define SMEM_FLOATS ((5888u + 512u) / 4u)

// ---------------------------------------------------------------------------
// Main kernel: one warp per ray, 4 warps / block (128 threads).
// ---------------------------------------------------------------------------
__global__ __launch_bounds__(128, 2)
void lidar_render(const float* __restrict__ rays_o,
                  const float* __restrict__ rays_d,
                  const float* __restrict__ W1,
                  const float* __restrict__ Wsig,
                  const float* __restrict__ Wa1,
                  const float* __restrict__ ba1,
                  const float* __restrict__ Wa2,
                  float* __restrict__ out, int N) {
    __shared__ __align__(16) float smf[SMEM_FLOATS];

    const int tid = threadIdx.x;
    if (tid < 32) {
        smf[O_W1R0 / 4 + tid] = W1[tid];
        smf[O_W1R1 / 4 + tid] = W1[32 + tid];
        smf[O_W1R2 / 4 + tid] = W1[64 + tid];
        smf[O_B1T  / 4 + tid] = g_b1t[tid];
        smf[O_WSIG / 4 + tid] = Wsig[tid];
        smf[O_WX0  / 4 + tid] = Wa1[tid];
        smf[O_WX1  / 4 + tid] = Wa1[32 + tid];
        smf[O_WX2  / 4 + tid] = Wa1[64 + tid];
        smf[O_WD0  / 4 + tid] = Wa1[96 + tid];
        smf[O_WD1  / 4 + tid] = Wa1[128 + tid];
        smf[O_WD2  / 4 + tid] = Wa1[160 + tid];
        smf[O_BA1  / 4 + tid] = ba1[tid];
        smf[O_WA2A / 4 + tid] = Wa2[tid * 2 + 0];
        smf[O_WA2B / 4 + tid] = Wa2[tid * 2 + 1];
    }
    for (int i = tid; i < 1024; i += 128)
        smf[O_WC / 4 + i] = g_Wc[i];
    __syncthreads();

    const int warp = tid >> 5;
    const int lane = tid & 31;
    const int ray  = blockIdx.x * 4 + warp;
    if (ray >= N) return;

    const float ox = rays_o[ray * 3 + 0];
    const float oy = rays_o[ray * 3 + 1];
    const float oz = rays_o[ray * 3 + 2];
    const float dx = rays_d[ray * 3 + 0];
    const float dy = rays_d[ray * 3 + 1];
    const float dz = rays_d[ray * 3 + 2];

    // per-ray attr bias: ba1 + rd @ Wa1[3:6]
    smf[O_DIRB / 4 + warp * 32 + lane] = smf[O_BA1 / 4 + lane]
        + dx * smf[O_WD0 / 4 + lane] + dy * smf[O_WD1 / 4 + lane]
        + dz * smf[O_WD2 / 4 + lane];
    __syncwarp();

    const unsigned base  = (unsigned)__cvta_generic_to_shared(smf);
    const unsigned bdirb = base + O_DIRB + warp * 128;

    const float ZSTEP = 0.8f / 511.f;
    float Tcarry = 1.f;
    float depth = 0.f, img0 = 0.f, img1 = 0.f, wsum = 0.f;

#pragma unroll 1
    for (int chunk = 0; chunk < CHUNKS; chunk++) {
        const int   sA = chunk * 64 + lane;
        const int   sB = sA + 32;
        const float zA = fmaf(ZSTEP, (float)sA, 0.01f);
        const float zB = fmaf(ZSTEP, (float)sB, 0.01f);
        const float xA  = fminf(fmaxf(fmaf(dx, zA, ox), -1.f), 1.f);
        const float yA  = fminf(fmaxf(fmaf(dy, zA, oy), -1.f), 1.f);
        const float zcA = fminf(fmaxf(fmaf(dz, zA, oz), -1.f), 1.f);
        const float xB  = fminf(fmaxf(fmaf(dx, zB, ox), -1.f), 1.f);
        const float yB  = fminf(fmaxf(fmaf(dy, zB, oy), -1.f), 1.f);
        const float zcB = fminf(fmaxf(fmaf(dz, zB, oz), -1.f), 1.f);

        const u64 xxA = pk2(xA, xA), yyA = pk2(yA, yA), zzA = pk2(zcA, zcA);
        const u64 xxB = pk2(xB, xB), yyB = pk2(yB, yB), zzB = pk2(zcB, zcB);

        // --- density hidden layer + sigma head (both steps, shared loads) ---
        float hA[32], hB[32];
        u64 sgA = 0ULL, sgB = 0ULL;
#pragma unroll
        for (int k = 0; k < 8; k++) {
            u64 w0a, w0b, w1a, w1b, w2a, w2b, ba, bb, sa, sb;
            lds16(base + O_W1R0 + k * 16, w0a, w0b);
            lds16(base + O_W1R1 + k * 16, w1a, w1b);
            lds16(base + O_W1R2 + k * 16, w2a, w2b);
            lds16(base + O_B1T  + k * 16, ba, bb);
            lds16(base + O_WSIG + k * 16, sa, sb);
            u64 vA0 = relu2(ffma2(xxA, w0a, ffma2(yyA, w1a, ffma2(zzA, w2a, ba))));
            u64 vA1 = relu2(ffma2(xxA, w0b, ffma2(yyA, w1b, ffma2(zzA, w2b, bb))));
            u64 vB0 = relu2(ffma2(xxB, w0a, ffma2(yyB, w1a, ffma2(zzB, w2a, ba))));
            u64 vB1 = relu2(ffma2(xxB, w0b, ffma2(yyB, w1b, ffma2(zzB, w2b, bb))));
            float2 fA0 = up2(vA0), fA1 = up2(vA1), fB0 = up2(vB0), fB1 = up2(vB1);
            hA[4*k+0] = fA0.x; hA[4*k+1] = fA0.y; hA[4*k+2] = fA1.x; hA[4*k+3] = fA1.y;
            hB[4*k+0] = fB0.x; hB[4*k+1] = fB0.y; hB[4*k+2] = fB1.x; hB[4*k+3] = fB1.y;
            sgA = ffma2(vA0, sa, sgA); sgA = ffma2(vA1, sb, sgA);
            sgB = ffma2(vB0, sa, sgB); sgB = ffma2(vB1, sb, sgB);
        }
        const float2 sA2 = up2(sgA), sB2 = up2(sgB);
        const float sigA = sA2.x + sA2.y;
        const float sigB = sB2.x + sB2.y;

        // softplus -> alpha (delta const except global last step)
        const float sigmaA = fmaxf(sigA, 0.f) + __logf(1.f + __expf(-fabsf(sigA)));
        const float sigmaB = fmaxf(sigB, 0.f) + __logf(1.f + __expf(-fabsf(sigB)));
        const float deltaB = (sB == 511) ? (0.8f / 512.f) : ZSTEP;
        float qA = __expf(-ZSTEP  * sigmaA);
        float qB = __expf(-deltaB * sigmaB);
        const float alphaA = 1.f - qA;
        const float alphaB = 1.f - qB;
        qA += 1e-15f; qB += 1e-15f;

        // --- attr MLP init: dirb + xyz @ Wa1[0:3] (both steps) ---
        u64 accA[16], accB[16];
#pragma unroll
        for (int k = 0; k < 8; k++) {
            u64 xa, xb, ya, yb, za, zb, da, db;
            lds16(base + O_WX0 + k * 16, xa, xb);
            lds16(base + O_WX1 + k * 16, ya, yb);
            lds16(base + O_WX2 + k * 16, za, zb);
            lds16(bdirb + k * 16, da, db);
            accA[2*k+0] = ffma2(xxA, xa, ffma2(yyA, ya, ffma2(zzA, za, da)));
            accA[2*k+1] = ffma2(xxA, xb, ffma2(yyA, yb, ffma2(zzA, zb, db)));
            accB[2*k+0] = ffma2(xxB, xa, ffma2(yyB, ya, ffma2(zzB, za, da)));
            accB[2*k+1] = ffma2(xxB, xb, ffma2(yyB, yb, ffma2(zzB, zb, db)));
        }

        // --- fused 32x32 GEMV: acc += h @ Wc (both steps share row loads) ---
#pragma unroll
        for (int j = 0; j < 32; j++) {
            const u64 hjA = pk2(hA[j], hA[j]);
            const u64 hjB = pk2(hB[j], hB[j]);
            const unsigned row = base + O_WC + j * 128;
#pragma unroll
            for (int m = 0; m < 4; m++) {
                u64 p0, p1, p2, p3;
                lds16(row + m * 32,      p0, p1);
                lds16(row + m * 32 + 16, p2, p3);
                accA[4*m+0] = ffma2(hjA, p0, accA[4*m+0]);
                accA[4*m+1] = ffma2(hjA, p1, accA[4*m+1]);
                accA[4*m+2] = ffma2(hjA, p2, accA[4*m+2]);
                accA[4*m+3] = ffma2(hjA, p3, accA[4*m+3]);
                accB[4*m+0] = ffma2(hjB, p0, accB[4*m+0]);
                accB[4*m+1] = ffma2(hjB, p1, accB[4*m+1]);
                accB[4*m+2] = ffma2(hjB, p2, accB[4*m+2]);
                accB[4*m+3] = ffma2(hjB, p3, accB[4*m+3]);
            }
        }

        // --- attr head: relu then @ Wa2 (both steps) ---
        u64 oA0 = 0ULL, oA1 = 0ULL, oB0 = 0ULL, oB1 = 0ULL;
#pragma unroll
        for (int k = 0; k < 8; k++) {
            u64 wa0, wa1v, wb0, wb1v;
            lds16(base + O_WA2A + k * 16, wa0, wa1v);
            lds16(base + O_WA2B + k * 16, wb0, wb1v);
            const u64 rA0 = relu2(accA[2*k+0]), rA1 = relu2(accA[2*k+1]);
            const u64 rB0 = relu2(accB[2*k+0]), rB1 = relu2(accB[2*k+1]);
            oA0 = ffma2(rA0, wa0, oA0); oA0 = ffma2(rA1, wa1v, oA0);
            oA1 = ffma2(rA0, wb0, oA1); oA1 = ffma2(rA1, wb1v, oA1);
            oB0 = ffma2(rB0, wa0, oB0); oB0 = ffma2(rB1, wa1v, oB0);
            oB1 = ffma2(rB0, wb0, oB1); oB1 = ffma2(rB1, wb1v, oB1);
        }
        const float2 tA0 = up2(oA0), tA1 = up2(oA1);
        const float2 tB0 = up2(oB0), tB1 = up2(oB1);
        const float aA0 = 1.f / (1.f + __expf(-(tA0.x + tA0.y)));
        const float aA1 = 1.f / (1.f + __expf(-(tA1.x + tA1.y)));
        const float aB0 = 1.f / (1.f + __expf(-(tB0.x + tB0.y)));
        const float aB1 = 1.f / (1.f + __expf(-(tB1.x + tB1.y)));

        // --- transmittance scans: steps A (s..s+31) then B (s+32..s+63) ---
        float PA = qA;
#pragma unroll
        for (int off = 1; off < 32; off <<= 1) {
            const float v = __shfl_up_sync(0xffffffffu, PA, off);
            if (lane >= off) PA *= v;
        }
        float PexA = __shfl_up_sync(0xffffffffu, PA, 1);
        if (lane == 0) PexA = 1.f;
        const float wA = alphaA * Tcarry * PexA;
        const float Tmid = Tcarry * __shfl_sync(0xffffffffu, PA, 31);

        float PB = qB;
#pragma unroll
        for (int off = 1; off < 32; off <<= 1) {
            const float v = __shfl_up_sync(0xffffffffu, PB, off);
            if (lane >= off) PB *= v;
        }
        float PexB = __shfl_up_sync(0xffffffffu, PB, 1);
        if (lane == 0) PexB = 1.f;
        const float wB = alphaB * Tmid * PexB;
        Tcarry = Tmid * __shfl_sync(0xffffffffu, PB, 31);

        depth = fmaf(wA, zA, fmaf(wB, zB, depth));
        img0  = fmaf(wA, aA0, fmaf(wB, aB0, img0));
        img1  = fmaf(wA, aA1, fmaf(wB, aB1, img1));
        wsum += wA + wB;
    }

    // warp reduction, lane 0 writes
#pragma unroll
    for (int off = 16; off; off >>= 1) {
        depth += __shfl_xor_sync(0xffffffffu, depth, off);
        img0  += __shfl_xor_sync(0xffffffffu, img0, off);
        img1  += __shfl_xor_sync(0xffffffffu, img1, off);
        wsum  += __shfl_xor_sync(0xffffffffu, wsum, off);
    }
    if (lane == 0) {
        out[ray]             = depth;        // depth        [N]
        out[N + ray * 2 + 0] = img0;         // image        [N,2]
        out[N + ray * 2 + 1] = img1;
        out[3 * N + ray]     = wsum;         // weights_sum  [N]
    }
}

// ---------------------------------------------------------------------------
// Launch. Inputs (metadata order):
// 0 rays_o  1 rays_d  2 time  3 W1  4 b1  5 Wsig  6 Wfeat  7 Wa1  8 ba1
// 9 Wa2  10 num_steps
// ---------------------------------------------------------------------------
extern "C" void kernel_launch(void* const* d_in, const int* in_sizes, int n_in,
                              void* d_out, int out_size) {
    const float* rays_o = (const float*)d_in[0];
    const float* rays_d = (const float*)d_in[1];
    const float* timep  = (const float*)d_in[2];
    const float* W1     = (const float*)d_in[3];
    const float* b1     = (const float*)d_in[4];
    const float* Wsig   = (const float*)d_in[5];
    const float* Wfeat  = (const float*)d_in[6];
    const float* Wa1    = (const float*)d_in[7];
    const float* ba1    = (const float*)d_in[8];
    const float* Wa2    = (const float*)d_in[9];

    const int N = in_sizes[0] / 3;   // 8192

    lidar_precompute_kernel<<<1, 1024>>>(W1, b1, timep, Wfeat, Wa1);
    lidar_render<<<(N + 3) / 4, 128>>>(rays_o, rays_d, W1, Wsig, Wa1,
                                       ba1, Wa2, (float*)d_out, N);
}

// round 6
// speedup vs baseline: 1.7798x; 1.0416x over previous
#include <cuda_runtime.h>
#include <cuda_bf16.h>

// LiDAR volume renderer, fused, FFMA2 (packed f32x2), 2 steps per lane.
// N=8192 rays, S=512 steps, H=32, OUT=2. One warp per ray.
// R5: Wa1[0:3] folded into extended 35x32 Wc; __launch_bounds__(128,3).
//
// Fusions:
//   WcExt rows 0..31 = Wfeat @ Wa1[6:22]   (precomputed per launch)
//   WcExt rows 32..34 = Wa1[0:3] (xyz rows; "h" for them is x,y,z splats)
//   b1t  = b1 + t * W1[3]
//   dirb = ba1 + rd @ Wa1[3:6] (per ray)

#define CHUNKS 8

typedef unsigned long long u64;

__device__ float g_Wc[35 * 32];
__device__ float g_b1t[32];

// ---------------------------------------------------------------------------
__global__ void lidar_precompute_kernel(const float* __restrict__ W1,
                                        const float* __restrict__ b1,
                                        const float* __restrict__ timep,
                                        const float* __restrict__ Wfeat,
                                        const float* __restrict__ Wa1) {
    int i = threadIdx.x;          // 0..1023
    int r = i >> 5;
    int c = i & 31;
    float acc = 0.f;
#pragma unroll
    for (int k = 0; k < 16; k++)
        acc = fmaf(Wfeat[r * 16 + k], Wa1[(6 + k) * 32 + c], acc);
    g_Wc[i] = acc;
    if (i < 96)                       // rows 32..34 = Wa1 rows 0..2 (xyz)
        g_Wc[1024 + i] = Wa1[i];
    if (i < 32)
        g_b1t[i] = fmaf(timep[0], W1[3 * 32 + i], b1[i]);
}

// ---------------------------------------------------------------------------
// packed f32x2 helpers
// ---------------------------------------------------------------------------
__device__ __forceinline__ u64 pk2(float a, float b) {
    u64 r; asm("mov.b64 %0,{%1,%2};" : "=l"(r) : "f"(a), "f"(b)); return r;
}
__device__ __forceinline__ float2 up2(u64 v) {
    float2 f; asm("mov.b64 {%0,%1},%2;" : "=f"(f.x), "=f"(f.y) : "l"(v)); return f;
}
__device__ __forceinline__ u64 ffma2(u64 a, u64 b, u64 c) {
    u64 d; asm("fma.rn.f32x2 %0,%1,%2,%3;" : "=l"(d) : "l"(a), "l"(b), "l"(c)); return d;
}
__device__ __forceinline__ void lds16(unsigned a, u64& p0, u64& p1) {
    asm volatile("ld.shared.v2.b64 {%0,%1},[%2];" : "=l"(p0), "=l"(p1) : "r"(a));
}
__device__ __forceinline__ u64 relu2(u64 v) {
    float2 f = up2(v);
    return pk2(fmaxf(f.x, 0.f), fmaxf(f.y, 0.f));
}

// smem layout: BYTE offsets, each 32-float block is 128B
#define O_W1R0  0u
#define O_W1R1  128u
#define O_W1R2  256u
#define O_B1T   384u
#define O_WSIG  512u
#define O_WA2A  640u
#define O_WA2B  768u
#define O_BA1   896u
#define O_WD0   1024u
#define O_WD1   1152u
#define O_WD2   1280u
#define O_WC    1408u          // 35 rows x 128B = 4480 bytes
#define O_DIRB  5888u          // 4 warps x 128B
#define SMEM_FLOATS ((5888u + 512u) / 4u)

// ---------------------------------------------------------------------------
// Main kernel: one warp per ray, 4 warps / block, 3 blocks / SM target.
// ---------------------------------------------------------------------------
__global__ __launch_bounds__(128, 3)
void lidar_render(const float* __restrict__ rays_o,
                  const float* __restrict__ rays_d,
                  const float* __restrict__ W1,
                  const float* __restrict__ Wsig,
                  const float* __restrict__ Wa1,
                  const float* __restrict__ ba1,
                  const float* __restrict__ Wa2,
                  float* __restrict__ out, int N) {
    __shared__ __align__(16) float smf[SMEM_FLOATS];

    const int tid = threadIdx.x;
    if (tid < 32) {
        smf[O_W1R0 / 4 + tid] = W1[tid];
        smf[O_W1R1 / 4 + tid] = W1[32 + tid];
        smf[O_W1R2 / 4 + tid] = W1[64 + tid];
        smf[O_B1T  / 4 + tid] = g_b1t[tid];
        smf[O_WSIG / 4 + tid] = Wsig[tid];
        smf[O_WD0  / 4 + tid] = Wa1[96 + tid];
        smf[O_WD1  / 4 + tid] = Wa1[128 + tid];
        smf[O_WD2  / 4 + tid] = Wa1[160 + tid];
        smf[O_BA1  / 4 + tid] = ba1[tid];
        smf[O_WA2A / 4 + tid] = Wa2[tid * 2 + 0];
        smf[O_WA2B / 4 + tid] = Wa2[tid * 2 + 1];
    }
    for (int i = tid; i < 35 * 32; i += 128)
        smf[O_WC / 4 + i] = g_Wc[i];
    __syncthreads();

    const int warp = tid >> 5;
    const int lane = tid & 31;
    const int ray  = blockIdx.x * 4 + warp;
    if (ray >= N) return;

    const float ox = rays_o[ray * 3 + 0];
    const float oy = rays_o[ray * 3 + 1];
    const float oz = rays_o[ray * 3 + 2];
    const float dx = rays_d[ray * 3 + 0];
    const float dy = rays_d[ray * 3 + 1];
    const float dz = rays_d[ray * 3 + 2];

    // per-ray attr bias: ba1 + rd @ Wa1[3:6]
    smf[O_DIRB / 4 + warp * 32 + lane] = smf[O_BA1 / 4 + lane]
        + dx * smf[O_WD0 / 4 + lane] + dy * smf[O_WD1 / 4 + lane]
        + dz * smf[O_WD2 / 4 + lane];
    __syncwarp();

    const unsigned base  = (unsigned)__cvta_generic_to_shared(smf);
    const unsigned bdirb = base + O_DIRB + warp * 128;

    const float ZSTEP = 0.8f / 511.f;
    float Tcarry = 1.f;
    float depth = 0.f, img0 = 0.f, img1 = 0.f, wsum = 0.f;

#pragma unroll 1
    for (int chunk = 0; chunk < CHUNKS; chunk++) {
        const int   sA = chunk * 64 + lane;
        const int   sB = sA + 32;
        const float zA = fmaf(ZSTEP, (float)sA, 0.01f);
        const float zB = fmaf(ZSTEP, (float)sB, 0.01f);
        const float xA  = fminf(fmaxf(fmaf(dx, zA, ox), -1.f), 1.f);
        const float yA  = fminf(fmaxf(fmaf(dy, zA, oy), -1.f), 1.f);
        const float zcA = fminf(fmaxf(fmaf(dz, zA, oz), -1.f), 1.f);
        const float xB  = fminf(fmaxf(fmaf(dx, zB, ox), -1.f), 1.f);
        const float yB  = fminf(fmaxf(fmaf(dy, zB, oy), -1.f), 1.f);
        const float zcB = fminf(fmaxf(fmaf(dz, zB, oz), -1.f), 1.f);

        const u64 xxA = pk2(xA, xA), yyA = pk2(yA, yA), zzA = pk2(zcA, zcA);
        const u64 xxB = pk2(xB, xB), yyB = pk2(yB, yB), zzB = pk2(zcB, zcB);

        // --- density hidden layer + sigma head (both steps, shared loads) ---
        float hA[32], hB[32];
        u64 sgA = 0ULL, sgB = 0ULL;
#pragma unroll
        for (int k = 0; k < 8; k++) {
            u64 w0a, w0b, w1a, w1b, w2a, w2b, ba, bb, sa, sb;
            lds16(base + O_W1R0 + k * 16, w0a, w0b);
            lds16(base + O_W1R1 + k * 16, w1a, w1b);
            lds16(base + O_W1R2 + k * 16, w2a, w2b);
            lds16(base + O_B1T  + k * 16, ba, bb);
            lds16(base + O_WSIG + k * 16, sa, sb);
            u64 vA0 = relu2(ffma2(xxA, w0a, ffma2(yyA, w1a, ffma2(zzA, w2a, ba))));
            u64 vA1 = relu2(ffma2(xxA, w0b, ffma2(yyA, w1b, ffma2(zzA, w2b, bb))));
            u64 vB0 = relu2(ffma2(xxB, w0a, ffma2(yyB, w1a, ffma2(zzB, w2a, ba))));
            u64 vB1 = relu2(ffma2(xxB, w0b, ffma2(yyB, w1b, ffma2(zzB, w2b, bb))));
            float2 fA0 = up2(vA0), fA1 = up2(vA1), fB0 = up2(vB0), fB1 = up2(vB1);
            hA[4*k+0] = fA0.x; hA[4*k+1] = fA0.y; hA[4*k+2] = fA1.x; hA[4*k+3] = fA1.y;
            hB[4*k+0] = fB0.x; hB[4*k+1] = fB0.y; hB[4*k+2] = fB1.x; hB[4*k+3] = fB1.y;
            sgA = ffma2(vA0, sa, sgA); sgA = ffma2(vA1, sb, sgA);
            sgB = ffma2(vB0, sa, sgB); sgB = ffma2(vB1, sb, sgB);
        }
        const float2 sA2 = up2(sgA), sB2 = up2(sgB);
        const float sigA = sA2.x + sA2.y;
        const float sigB = sB2.x + sB2.y;

        // softplus -> alpha (delta const except global last step)
        const float sigmaA = fmaxf(sigA, 0.f) + __logf(1.f + __expf(-fabsf(sigA)));
        const float sigmaB = fmaxf(sigB, 0.f) + __logf(1.f + __expf(-fabsf(sigB)));
        const float deltaB = (sB == 511) ? (0.8f / 512.f) : ZSTEP;
        float qA = __expf(-ZSTEP  * sigmaA);
        float qB = __expf(-deltaB * sigmaB);
        const float alphaA = 1.f - qA;
        const float alphaB = 1.f - qB;
        qA += 1e-15f; qB += 1e-15f;

        // --- attr MLP: acc = dirb; acc += [h | xyz] @ WcExt (35 rows) ---
        u64 accA[16], accB[16];
#pragma unroll
        for (int k = 0; k < 8; k++) {
            u64 da, db;
            lds16(bdirb + k * 16, da, db);
            accA[2*k+0] = da; accA[2*k+1] = db;
            accB[2*k+0] = da; accB[2*k+1] = db;
        }

#define WC_ROW(J, HJA, HJB)                                                   \
        {                                                                     \
            const unsigned row = base + O_WC + (J) * 128;                     \
            _Pragma("unroll")                                                 \
            for (int m = 0; m < 4; m++) {                                     \
                u64 p0, p1, p2, p3;                                           \
                lds16(row + m * 32,      p0, p1);                             \
                lds16(row + m * 32 + 16, p2, p3);                             \
                accA[4*m+0] = ffma2((HJA), p0, accA[4*m+0]);                  \
                accA[4*m+1] = ffma2((HJA), p1, accA[4*m+1]);                  \
                accA[4*m+2] = ffma2((HJA), p2, accA[4*m+2]);                  \
                accA[4*m+3] = ffma2((HJA), p3, accA[4*m+3]);                  \
                accB[4*m+0] = ffma2((HJB), p0, accB[4*m+0]);                  \
                accB[4*m+1] = ffma2((HJB), p1, accB[4*m+1]);                  \
                accB[4*m+2] = ffma2((HJB), p2, accB[4*m+2]);                  \
                accB[4*m+3] = ffma2((HJB), p3, accB[4*m+3]);                  \
            }                                                                 \
        }

#pragma unroll
        for (int j = 0; j < 32; j++) {
            const u64 hjA = pk2(hA[j], hA[j]);
            const u64 hjB = pk2(hB[j], hB[j]);
            WC_ROW(j, hjA, hjB)
        }
        WC_ROW(32, xxA, xxB)
        WC_ROW(33, yyA, yyB)
        WC_ROW(34, zzA, zzB)
#undef WC_ROW

        // --- attr head: relu then @ Wa2 (both steps) ---
        u64 oA0 = 0ULL, oA1 = 0ULL, oB0 = 0ULL, oB1 = 0ULL;
#pragma unroll
        for (int k = 0; k < 8; k++) {
            u64 wa0, wa1v, wb0, wb1v;
            lds16(base + O_WA2A + k * 16, wa0, wa1v);
            lds16(base + O_WA2B + k * 16, wb0, wb1v);
            const u64 rA0 = relu2(accA[2*k+0]), rA1 = relu2(accA[2*k+1]);
            const u64 rB0 = relu2(accB[2*k+0]), rB1 = relu2(accB[2*k+1]);
            oA0 = ffma2(rA0, wa0, oA0); oA0 = ffma2(rA1, wa1v, oA0);
            oA1 = ffma2(rA0, wb0, oA1); oA1 = ffma2(rA1, wb1v, oA1);
            oB0 = ffma2(rB0, wa0, oB0); oB0 = ffma2(rB1, wa1v, oB0);
            oB1 = ffma2(rB0, wb0, oB1); oB1 = ffma2(rB1, wb1v, oB1);
        }
        const float2 tA0 = up2(oA0), tA1 = up2(oA1);
        const float2 tB0 = up2(oB0), tB1 = up2(oB1);
        const float aA0 = 1.f / (1.f + __expf(-(tA0.x + tA0.y)));
        const float aA1 = 1.f / (1.f + __expf(-(tA1.x + tA1.y)));
        const float aB0 = 1.f / (1.f + __expf(-(tB0.x + tB0.y)));
        const float aB1 = 1.f / (1.f + __expf(-(tB1.x + tB1.y)));

        // --- transmittance scans: steps A (s..s+31) then B (s+32..s+63) ---
        float PA = qA;
#pragma unroll
        for (int off = 1; off < 32; off <<= 1) {
            const float v = __shfl_up_sync(0xffffffffu, PA, off);
            if (lane >= off) PA *= v;
        }
        float PexA = __shfl_up_sync(0xffffffffu, PA, 1);
        if (lane == 0) PexA = 1.f;
        const float wA = alphaA * Tcarry * PexA;
        const float Tmid = Tcarry * __shfl_sync(0xffffffffu, PA, 31);

        float PB = qB;
#pragma unroll
        for (int off = 1; off < 32; off <<= 1) {
            const float v = __shfl_up_sync(0xffffffffu, PB, off);
            if (lane >= off) PB *= v;
        }
        float PexB = __shfl_up_sync(0xffffffffu, PB, 1);
        if (lane == 0) PexB = 1.f;
        const float wB = alphaB * Tmid * PexB;
        Tcarry = Tmid * __shfl_sync(0xffffffffu, PB, 31);

        depth = fmaf(wA, zA, fmaf(wB, zB, depth));
        img0  = fmaf(wA, aA0, fmaf(wB, aB0, img0));
        img1  = fmaf(wA, aA1, fmaf(wB, aB1, img1));
        wsum += wA + wB;
    }

    // warp reduction, lane 0 writes
#pragma unroll
    for (int off = 16; off; off >>= 1) {
        depth += __shfl_xor_sync(0xffffffffu, depth, off);
        img0  += __shfl_xor_sync(0xffffffffu, img0, off);
        img1  += __shfl_xor_sync(0xffffffffu, img1, off);
        wsum  += __shfl_xor_sync(0xffffffffu, wsum, off);
    }
    if (lane == 0) {
        out[ray]             = depth;        // depth        [N]
        out[N + ray * 2 + 0] = img0;         // image        [N,2]
        out[N + ray * 2 + 1] = img1;
        out[3 * N + ray]     = wsum;         // weights_sum  [N]
    }
}

// ---------------------------------------------------------------------------
// Launch. Inputs (metadata order):
// 0 rays_o  1 rays_d  2 time  3 W1  4 b1  5 Wsig  6 Wfeat  7 Wa1  8 ba1
// 9 Wa2  10 num_steps
// ---------------------------------------------------------------------------
extern "C" void kernel_launch(void* const* d_in, const int* in_sizes, int n_in,
                              void* d_out, int out_size) {
    const float* rays_o = (const float*)d_in[0];
    const float* rays_d = (const float*)d_in[1];
    const float* timep  = (const float*)d_in[2];
    const float* W1     = (const float*)d_in[3];
    const float* b1     = (const float*)d_in[4];
    const float* Wsig   = (const float*)d_in[5];
    const float* Wfeat  = (const float*)d_in[6];
    const float* Wa1    = (const float*)d_in[7];
    const float* ba1    = (const float*)d_in[8];
    const float* Wa2    = (const float*)d_in[9];

    const int N = in_sizes[0] / 3;   // 8192

    lidar_precompute_kernel<<<1, 1024>>>(W1, b1, timep, Wfeat, Wa1);
    lidar_render<<<(N + 3) / 4, 128>>>(rays_o, rays_d, W1, Wsig, Wa1,
                                       ba1, Wa2, (float*)d_out, N);
}